// round 10
// baseline (speedup 1.0000x reference)
#include <cuda_runtime.h>
#include <math.h>

// Problem constants
#define HW      262144        // 512*512
#define NTILES  16384         // 2M pixels / 128-pixel tiles
#define NB      148           // persistent blocks (1 CTA/SM)
#define K       19
#define KC      1216          // 19*64
#define NSTAGE  4

// Scratch (no allocation allowed -> __device__ globals)
__device__ float g_psums[NB * KC];
__device__ int   g_pcnts[K * NB];        // [class][block]
__device__ float g_sums[KC];
__device__ int   g_cnt[K];

#define TILE_F   8192
// dyn smem: 4 tiles + order[4][128] + bstart/bcnt/bcur[4][19]
#define SMEM_BYTES (NSTAGE*TILE_F*4 + NSTAGE*128*4 + 3*NSTAGE*19*4 + 64)

// Named barriers: full[s] = id 1+s, empty[s] = id 5+s; count = all 896 threads.
#define BAR_SYNC(id)   asm volatile("bar.sync %0, %1;"   :: "r"(id), "r"(896) : "memory")
#define BAR_ARRIVE(id) asm volatile("bar.arrive %0, %1;" :: "r"(id), "r"(896) : "memory")

// ---------------------------------------------------------------------------
// K1: warp-specialized streaming centroid scatter-sum.
//   Roles (896 thr): wid 0..18 = class-owned accumulator warps (consumers);
//   wid 19 = label counting-sort warp; wid 20..27 = loader warps (producers).
//   4-stage smem ring, producer/consumer named barriers — NO block barrier.
//   Tile layout (per stage): row = pixel (64 floats), channel pair (c, c+32)
//   at float2 slot 2*((c&31)^(pixel>>2)) — conflict-free STS.64 / LDS.64.
// ---------------------------------------------------------------------------
__global__ __launch_bounds__(896, 1) void k1_kernel(const float* __restrict__ inp,
                                                    const int* __restrict__ tgt32) {
    extern __shared__ float sm[];
    float* tiles  = sm;                              // [4][8192]
    int*   order  = (int*)(sm + NSTAGE * TILE_F);    // [4][128]
    int*   bstart = order + NSTAGE * 128;            // [4][19]
    int*   bcnt   = bstart + NSTAGE * 19;            // [4][19]
    int*   bcur   = bcnt + NSTAGE * 19;              // [4][19]

    const int tid  = threadIdx.x;
    const int lane = tid & 31;
    const int wid  = tid >> 5;
    const int bid  = blockIdx.x;
    const int nblk = (NTILES - bid + NB - 1) / NB;   // tiles this block owns

    if (wid >= 20) {
        // ================= LOADER WARPS (wid 20..27) =================
        const int lw = wid - 20;      // 0..7; channels lw, lw+8, ..., lw+56
        const int q  = lane;          // pixel-quad 0..31
        float4 v[8];
        {   // preload tile j=0
            const int t = bid, b = t >> 11, hw0 = (t & 2047) << 7;
            const float* p = inp + ((size_t)b << 24) + hw0 + (q << 2) + (size_t)lw * HW;
            #pragma unroll
            for (int m = 0; m < 8; ++m)
                v[m] = __ldcs((const float4*)(p + (size_t)m * (8 * HW)));
        }
        for (int j = 0; j < nblk; ++j) {
            const int s = j & 3;
            if (j >= NSTAGE) BAR_SYNC(5 + s);        // wait stage empty
            float* r = tiles + s * TILE_F + (q << 8);  // pixel 4q row base
            #pragma unroll
            for (int m = 0; m < 4; ++m) {
                const int slot = 2 * ((lw + 8 * m) ^ q);
                float4 lo = v[m], hi = v[m + 4];
                *(float2*)(r +       slot) = make_float2(lo.x, hi.x);
                *(float2*)(r +  64 + slot) = make_float2(lo.y, hi.y);
                *(float2*)(r + 128 + slot) = make_float2(lo.z, hi.z);
                *(float2*)(r + 192 + slot) = make_float2(lo.w, hi.w);
            }
            BAR_ARRIVE(1 + s);                       // stage full
            if (j + 1 < nblk) {                      // prefetch next tile
                const int t = bid + (j + 1) * NB, b = t >> 11, hw0 = (t & 2047) << 7;
                const float* p = inp + ((size_t)b << 24) + hw0 + (q << 2) + (size_t)lw * HW;
                #pragma unroll
                for (int m = 0; m < 8; ++m)
                    v[m] = __ldcs((const float4*)(p + (size_t)m * (8 * HW)));
            }
        }
    } else if (wid == 19) {
        // ================= SORTER WARP =================
        int shift = 0;
        if (lane == 0) {     // int64 labels 0..18 have all-zero high words
            int all0 = 1;
            #pragma unroll
            for (int i = 0; i < 32; ++i)
                if (tgt32[2 * i + 1] != 0) all0 = 0;
            shift = all0;
        }
        shift = __shfl_sync(0xffffffffu, shift, 0);
        int lab0, lab1, lab2, lab3;
        {   // preload labels tile j=0
            const int t = bid, b = t >> 11, hw0 = (t & 2047) << 7;
            const int tb = (b << 18) + hw0;
            lab0 = tgt32[(size_t)(tb + lane)      << shift];
            lab1 = tgt32[(size_t)(tb + lane + 32) << shift];
            lab2 = tgt32[(size_t)(tb + lane + 64) << shift];
            lab3 = tgt32[(size_t)(tb + lane + 96) << shift];
        }
        for (int j = 0; j < nblk; ++j) {
            const int s = j & 3;
            if (j >= NSTAGE) BAR_SYNC(5 + s);
            int* bc = bcnt + s * 19;
            int* bs = bstart + s * 19;
            int* bu = bcur + s * 19;
            int* od = order + s * 128;
            int l0 = min(max(lab0, 0), 18), l1 = min(max(lab1, 0), 18);
            int l2 = min(max(lab2, 0), 18), l3 = min(max(lab3, 0), 18);
            if (lane < 19) bc[lane] = 0;
            __syncwarp();
            atomicAdd(&bc[l0], 1); atomicAdd(&bc[l1], 1);
            atomicAdd(&bc[l2], 1); atomicAdd(&bc[l3], 1);
            __syncwarp();
            int c = (lane < 19) ? bc[lane] : 0;
            int x = c;
            #pragma unroll
            for (int off = 1; off < 32; off <<= 1) {
                int y = __shfl_up_sync(0xffffffffu, x, off);
                if (lane >= off) x += y;
            }
            if (lane < 19) { bs[lane] = x - c; bu[lane] = x - c; }
            __syncwarp();
            int p0 = atomicAdd(&bu[l0], 1); od[p0] = lane;
            int p1 = atomicAdd(&bu[l1], 1); od[p1] = lane + 32;
            int p2 = atomicAdd(&bu[l2], 1); od[p2] = lane + 64;
            int p3 = atomicAdd(&bu[l3], 1); od[p3] = lane + 96;
            BAR_ARRIVE(1 + s);
            if (j + 1 < nblk) {
                const int t = bid + (j + 1) * NB, b = t >> 11, hw0 = (t & 2047) << 7;
                const int tb = (b << 18) + hw0;
                lab0 = tgt32[(size_t)(tb + lane)      << shift];
                lab1 = tgt32[(size_t)(tb + lane + 32) << shift];
                lab2 = tgt32[(size_t)(tb + lane + 64) << shift];
                lab3 = tgt32[(size_t)(tb + lane + 96) << shift];
            }
        }
    } else {
        // ================= CLASS WARPS (wid 0..18) =================
        float a0 = 0.f, a1 = 0.f, b0 = 0.f, b1 = 0.f;
        int ccnt = 0;
        for (int j = 0; j < nblk; ++j) {
            const int s = j & 3;
            BAR_SYNC(1 + s);                         // wait stage full
            const int base = bstart[s * 19 + wid];
            const int n    = bcnt[s * 19 + wid];
            const int* od  = order + s * 128;
            const float* tb = tiles + s * TILE_F;
            ccnt += n;
            int i = 0;
            for (; i + 2 <= n; i += 2) {             // two independent chains
                const int pA = od[base + i], pB = od[base + i + 1];
                float2 fA = *(const float2*)(tb + (pA << 6) + 2 * (lane ^ ((pA >> 2) & 31)));
                float2 fB = *(const float2*)(tb + (pB << 6) + 2 * (lane ^ ((pB >> 2) & 31)));
                a0 += fA.x; a1 += fA.y;
                b0 += fB.x; b1 += fB.y;
            }
            if (i < n) {
                const int pA = od[base + i];
                float2 fA = *(const float2*)(tb + (pA << 6) + 2 * (lane ^ ((pA >> 2) & 31)));
                a0 += fA.x; a1 += fA.y;
            }
            BAR_ARRIVE(5 + s);                       // stage empty
        }
        // write per-block partials
        g_psums[bid * KC + (wid << 6) + lane]      = a0 + b0;
        g_psums[bid * KC + (wid << 6) + 32 + lane] = a1 + b1;
        if (lane == 0) g_pcnts[wid * NB + bid] = ccnt;
    }
}

// ---------------------------------------------------------------------------
// K2: wide psums reduce + counts. Blocks 0..151: 2 float4-columns each,
// 128 threads/column, coalesced rows + smem tree. Block 152: count reduce.
// ---------------------------------------------------------------------------
__global__ __launch_bounds__(256) void k2_kernel() {
    const int tid = threadIdx.x;
    if (blockIdx.x == 152) {      // counts: 8 warps over 19 classes
        const int wid = tid >> 5, lane = tid & 31;
        for (int cls = wid; cls < K; cls += 8) {
            int s = 0;
            for (int p = lane; p < NB; p += 32) s += g_pcnts[cls * NB + p];
            #pragma unroll
            for (int off = 16; off > 0; off >>= 1) s += __shfl_xor_sync(0xffffffffu, s, off);
            if (lane == 0) g_cnt[cls] = s;
        }
        return;
    }
    __shared__ float4 red[256];
    const int half = tid >> 7;                 // which of the 2 columns
    const int r    = tid & 127;                // row lane within column
    const int col  = (blockIdx.x << 1) + half; // 0..303
    const float4* ps = (const float4*)g_psums;
    float4 s = make_float4(0.f, 0.f, 0.f, 0.f);
    for (int row = r; row < NB; row += 128) {
        float4 v = ps[row * 304 + col];
        s.x += v.x; s.y += v.y; s.z += v.z; s.w += v.w;
    }
    red[tid] = s;
    __syncthreads();
    #pragma unroll
    for (int off = 64; off > 0; off >>= 1) {
        if (r < off) {
            float4 o = red[tid + off];
            s.x += o.x; s.y += o.y; s.z += o.z; s.w += o.w;
            red[tid] = s;
        }
        __syncthreads();
    }
    if (r == 0) ((float4*)g_sums)[col] = red[half << 7];
}

// ---------------------------------------------------------------------------
// K3: centroids + norms (warp-per-class) + cosine-embedding loss. 1 block.
// ---------------------------------------------------------------------------
__global__ __launch_bounds__(640) void k3_kernel(float* __restrict__ out) {
    __shared__ float cen[KC];
    __shared__ float nrm[K];
    __shared__ int   cnts[K];
    __shared__ float red[512];
    const int tid = threadIdx.x;
    const int wid = tid >> 5, lane = tid & 31;

    if (tid < K) cnts[tid] = g_cnt[tid];
    __syncthreads();
    if (tid < 304) {   // float4 load + centroid divide (16 float4 per class)
        float inv = 1.0f / fmaxf((float)cnts[tid >> 4], 1.0f);
        float4 v = ((const float4*)g_sums)[tid];
        ((float4*)cen)[tid] = make_float4(v.x * inv, v.y * inv, v.z * inv, v.w * inv);
    }
    __syncthreads();
    if (wid < K) {     // warp per class: 2 elems/lane + shfl tree
        float x0 = cen[(wid << 6) + lane], x1 = cen[(wid << 6) + 32 + lane];
        float nn = x0 * x0 + x1 * x1;
        #pragma unroll
        for (int off = 16; off > 0; off >>= 1) nn += __shfl_xor_sync(0xffffffffu, nn, off);
        if (lane == 0) nrm[wid] = fmaxf(sqrtf(nn), 1e-8f);
    }
    __syncthreads();
    if (tid < 304) {
        float inv = 1.0f / nrm[tid >> 4];
        float4 v = ((const float4*)cen)[tid];
        ((float4*)cen)[tid] = make_float4(v.x * inv, v.y * inv, v.z * inv, v.w * inv);
    }
    __syncthreads();

    float val = 0.f;
    if (tid < K * K) {
        const int k1i = tid / K, k2i = tid % K;
        float dot = 0.f;
        #pragma unroll
        for (int c = 0; c < 64; ++c)
            dot += cen[(k1i << 6) + c] * cen[(k2i << 6) + c];
        val = (k1i == k2i) ? (1.0f - dot) : fmaxf(dot, 0.0f);
    }
    if (tid < 512) red[tid] = val;
    __syncthreads();
    #pragma unroll
    for (int off = 256; off > 0; off >>= 1) {
        if (tid < off) red[tid] += red[tid + off];
        __syncthreads();
    }
    if (tid == 0) out[0] = red[0] / 6859.0f;   // K^3
}

// ---------------------------------------------------------------------------
extern "C" void kernel_launch(void* const* d_in, const int* in_sizes, int n_in,
                              void* d_out, int out_size) {
    // Select pointers by element count (inputs: 134M, targets: 2M) — robust to order.
    int ii = 0, ti = 1;
    if (n_in >= 2 && in_sizes[1] > in_sizes[0]) { ii = 1; ti = 0; }
    const float* inp = (const float*)d_in[ii];
    const int* tgt32 = (const int*)d_in[ti];
    cudaFuncSetAttribute(k1_kernel, cudaFuncAttributeMaxDynamicSharedMemorySize, SMEM_BYTES);
    k1_kernel<<<NB, 896, SMEM_BYTES>>>(inp, tgt32);
    k2_kernel<<<153, 256>>>();
    k3_kernel<<<1, 640>>>((float*)d_out);
}